// round 5
// baseline (speedup 1.0000x reference)
#include <cuda_runtime.h>
#include <cstdint>

#define BSZ 2
#define LEN 2048
#define NHD 24
#define DH  64
#define DS  128

#define NPAIR (BSZ*NHD)     // 48
#define TC    64            // chunk length
#define NCH   (LEN/TC)      // 32
#define THREADS 256

#define WPITCH 68           // W tile pitch (floats), 272B rows (16B aligned)
#define XP1    68           // pass1 x pitch

// ------------- device scratch (no allocation allowed) -------------
__device__ float g_S[NPAIR*NCH*DH*DS];    // chunk contributions (50 MB)
__device__ float g_H[NPAIR*NCH*DH*DS];    // chunk-start states   (50 MB)
__device__ float g_P[NPAIR*NCH];          // chunk decay products

__device__ __forceinline__ int swz(int r) { return ((r >> 3) ^ r) & 7; }

__device__ __forceinline__ float neg_sp_abs(float a, float d) {
    float v  = a + d;
    float sp = (v > 20.f) ? v : log1pf(expf(v));   // stable softplus
    return -sp * fabsf(a);                          // log(a_bar) <= 0
}

// inclusive scan of buf[0..TC) (all threads participate)
__device__ __forceinline__ void scan_lcp(float* buf, int tid) {
    for (int off = 1; off < TC; off <<= 1) {
        float v = 0.f;
        if (tid < TC && tid >= off) v = buf[tid - off];
        __syncthreads();
        if (tid < TC) buf[tid] += v;
        __syncthreads();
    }
}

// =================================================================
// Pass 1: S_j[d,s] = sum_t w_t x[t,d] B[t,s],  w_t = exp(lcp_end - lcp_t)
// =================================================================
__global__ __launch_bounds__(THREADS, 2)
void pass1_kernel(const float* __restrict__ x,
                  const float* __restrict__ Bm,
                  const float* __restrict__ A,
                  const float* __restrict__ dp) {
    extern __shared__ float sm[];
    float*  Bsh  = sm;                    // 64 x 128 swizzled
    float*  xsh  = Bsh + TC * DS;         // 64 x XP1
    float*  lcp  = xsh + TC * XP1;        // TC
    float*  lw   = lcp + TC;              // TC
    float4* Bsh4 = (float4*)Bsh;

    const int tid  = threadIdx.x;
    const int ch   = blockIdx.x;
    const int pair = blockIdx.y;
    const int b    = pair / NHD;
    const int hh   = pair % NHD;
    const size_t rowbase = ((size_t)b * LEN + ch * TC) * NHD + hh;

    for (int i = tid; i < TC * (DS/4); i += THREADS) {
        int t = i >> 5, c = i & 31;
        Bsh4[t * 32 + (c ^ swz(t))] =
            ((const float4*)(Bm + (rowbase + (size_t)t*NHD) * DS))[c];
    }
    for (int i = tid; i < TC * (DH/4); i += THREADS) {
        int t = i >> 4, c = i & 15;
        ((float4*)(xsh + t * XP1))[c] =
            ((const float4*)(x + (rowbase + (size_t)t*NHD) * DH))[c];
    }
    if (tid < TC) lcp[tid] = neg_sp_abs(A[rowbase + (size_t)tid * NHD], dp[hh]);
    __syncthreads();
    scan_lcp(lcp, tid);
    if (tid < TC) lw[tid] = __expf(lcp[TC-1] - lcp[tid]);
    if (tid == 0) g_P[pair*NCH + ch] = __expf(lcp[TC-1]);
    __syncthreads();
    for (int i = tid; i < TC * DH; i += THREADS) {       // fold w_t into x
        int t = i >> 6, d = i & 63;
        xsh[t * XP1 + d] *= lw[t];
    }
    __syncthreads();

    const int ty = tid >> 4, tx = tid & 15;   // 4 d x 8 s per thread
    float acc[4][8];
    #pragma unroll
    for (int i = 0; i < 4; ++i)
        #pragma unroll
        for (int j = 0; j < 8; ++j) acc[i][j] = 0.f;

    #pragma unroll 4
    for (int t = 0; t < TC; ++t) {
        const int s = swz(t);
        float4 xv = *(const float4*)(xsh + t * XP1 + 4 * ty);
        float4 b0 = Bsh4[t * 32 + ((2*tx)   ^ s)];
        float4 b1 = Bsh4[t * 32 + ((2*tx+1) ^ s)];
        float xx[4] = {xv.x, xv.y, xv.z, xv.w};
        float bb[8] = {b0.x, b0.y, b0.z, b0.w, b1.x, b1.y, b1.z, b1.w};
        #pragma unroll
        for (int i = 0; i < 4; ++i)
            #pragma unroll
            for (int j = 0; j < 8; ++j) acc[i][j] += xx[i] * bb[j];
    }

    float* Sdst = g_S + ((size_t)(pair*NCH + ch)) * DH * DS;
    #pragma unroll
    for (int i = 0; i < 4; ++i) {
        float* p = Sdst + (4*ty + i) * DS + 8*tx;
        ((float4*)p)[0] = make_float4(acc[i][0], acc[i][1], acc[i][2], acc[i][3]);
        ((float4*)p)[1] = make_float4(acc[i][4], acc[i][5], acc[i][6], acc[i][7]);
    }
}

// =================================================================
// Pass 2: H scan over chunks, parallel over (pair, 8 segments)
// =================================================================
__global__ __launch_bounds__(THREADS, 8)
void pass2_kernel() {
    const int pair = blockIdx.x;
    const int seg  = blockIdx.y;
    const int idx  = seg * THREADS + threadIdx.x;   // float4 index in [0,2048)
    const float* Pp = g_P + pair * NCH;

    float4 Hr = make_float4(0.f, 0.f, 0.f, 0.f);
    #pragma unroll 4
    for (int ch = 0; ch < NCH; ++ch) {
        const size_t b4 = (size_t)(pair*NCH + ch) * (DH*DS/4) + idx;
        float4 s4 = ((const float4*)g_S)[b4];
        ((float4*)g_H)[b4] = Hr;
        const float P = Pp[ch];
        Hr.x = P*Hr.x + s4.x;  Hr.y = P*Hr.y + s4.y;
        Hr.z = P*Hr.z + s4.z;  Hr.w = P*Hr.w + s4.w;
    }
}

// =================================================================
// Pass 3:  R = C . [B;H]^T; W masked+decayed -> smem; Y1 in regs;
//          Y = Y1 + W . x  (causal)
// smem = 64KB (D) + 32KB (C, later aliased by W) + 16KB (x) = 112KB
// =================================================================
__global__ __launch_bounds__(THREADS, 2)
void pass3_kernel(const float* __restrict__ x,
                  const float* __restrict__ Bm,
                  const float* __restrict__ Cm,
                  const float* __restrict__ A,
                  const float* __restrict__ dp,
                  float* __restrict__ out) {
    extern __shared__ float sm[];
    float*  Dsh  = sm;                    // 128 x 128 swizzled (B rows 0..63, H rows 64..127)
    float*  Csh  = Dsh + 2 * TC * DS;     // 64 x 128 swizzled; aliased by Wsh after GEMM1
    float*  xsh  = Csh + TC * DS;         // 64 x 64
    float*  Wsh  = Csh;                   // 64 x WPITCH  (4352 <= 8192 floats)
    float4* Dsh4 = (float4*)Dsh;
    float4* Csh4 = (float4*)Csh;

    const int tid  = threadIdx.x;
    const int ty   = tid >> 4;            // 0..15 : 4 t-rows
    const int tx   = tid & 15;            // 0..15 : 4 s-cols and 4 d-cols
    const int ch   = blockIdx.x;
    const int pair = blockIdx.y;
    const int b    = pair / NHD;
    const int hh   = pair % NHD;
    const size_t rowbase = ((size_t)b * LEN + ch * TC) * NHD + hh;

    // ---- phase 0: decay prefix in Csh[0:64] (before C is loaded) ----
    if (tid < TC)
        Csh[tid] = neg_sp_abs(A[rowbase + (size_t)tid * NHD], dp[hh]);
    __syncthreads();
    // raw single-step logs for the W-factor chain (read before scan mutates)
    float g1 = Csh[4*tx + 1], g2 = Csh[4*tx + 2], g3 = Csh[4*tx + 3];
    scan_lcp(Csh, tid);
    float lt[4], elcv[4];
    #pragma unroll
    for (int i = 0; i < 4; ++i) {
        lt[i]   = Csh[4*ty + i];
        elcv[i] = __expf(lt[i]);
    }
    const float ls = Csh[4*tx];
    g1 = fminf(__expf(-g1), 1e30f);
    g2 = fminf(__expf(-g2), 1e30f);
    g3 = fminf(__expf(-g3), 1e30f);
    __syncthreads();

    // ---- load tiles ----
    for (int i = tid; i < TC * (DS/4); i += THREADS) {
        int t = i >> 5, c = i & 31;
        Csh4[t * 32 + (c ^ swz(t))] =
            ((const float4*)(Cm + (rowbase + (size_t)t*NHD) * DS))[c];
        Dsh4[t * 32 + (c ^ swz(t))] =
            ((const float4*)(Bm + (rowbase + (size_t)t*NHD) * DS))[c];
    }
    const float4* Hsrc = (const float4*)(g_H + ((size_t)(pair*NCH + ch)) * DH * DS);
    for (int i = tid; i < DH * (DS/4); i += THREADS) {
        int d = i >> 5, c = i & 31, r = 64 + d;
        Dsh4[r * 32 + (c ^ swz(r))] = Hsrc[i];
    }
    for (int i = tid; i < TC * (DH/4); i += THREADS) {
        int t = i >> 4, c = i & 15;
        ((float4*)(xsh + t * DH))[c] =
            ((const float4*)(x + (rowbase + (size_t)t*NHD) * DH))[c];
    }
    __syncthreads();

    // ---- GEMM1: per thread 4t x (4 W-cols + 4 Y-cols), k = 128 ----
    int swc[4], swd[4];
    #pragma unroll
    for (int i = 0; i < 4; ++i) swc[i] = swz(4*ty + i);
    #pragma unroll
    for (int j = 0; j < 4; ++j) swd[j] = swz(4*tx + j);   // == swz(64+4tx+j)

    float wa[4][4], ya[4][4];
    #pragma unroll
    for (int i = 0; i < 4; ++i)
        #pragma unroll
        for (int j = 0; j < 4; ++j) { wa[i][j] = 0.f; ya[i][j] = 0.f; }

    #pragma unroll 2
    for (int c = 0; c < 32; ++c) {
        float4 Cf[4], Bf[4], Hf[4];
        #pragma unroll
        for (int i = 0; i < 4; ++i) Cf[i] = Csh4[(4*ty + i) * 32 + (c ^ swc[i])];
        #pragma unroll
        for (int j = 0; j < 4; ++j) Bf[j] = Dsh4[(4*tx + j) * 32 + (c ^ swd[j])];
        #pragma unroll
        for (int j = 0; j < 4; ++j) Hf[j] = Dsh4[(64 + 4*tx + j) * 32 + (c ^ swd[j])];
        #pragma unroll
        for (int i = 0; i < 4; ++i)
            #pragma unroll
            for (int j = 0; j < 4; ++j) {
                wa[i][j] += Cf[i].x*Bf[j].x + Cf[i].y*Bf[j].y
                          + Cf[i].z*Bf[j].z + Cf[i].w*Bf[j].w;
                ya[i][j] += Cf[i].x*Hf[j].x + Cf[i].y*Hf[j].y
                          + Cf[i].z*Hf[j].z + Cf[i].w*Hf[j].w;
            }
    }
    __syncthreads();     // everyone done reading Csh before W overwrites it

    // ---- epilogue: W = mask * exp(lcp_t - lcp_s) * wa  -> Wsh ----
    if (tx <= ty) {
        const float f1 = g1;
        const float f2 = fminf(f1 * g2, 1e30f);
        const float f3 = fminf(f2 * g3, 1e30f);
        #pragma unroll
        for (int i = 0; i < 4; ++i) {
            const int   t  = 4*ty + i;
            const float se = __expf(lt[i] - ls);          // <= 1
            float4 wv;
            wv.x = (4*tx     <= t) ? se      * wa[i][0] : 0.f;
            wv.y = (4*tx + 1 <= t) ? se * f1 * wa[i][1] : 0.f;
            wv.z = (4*tx + 2 <= t) ? se * f2 * wa[i][2] : 0.f;
            wv.w = (4*tx + 3 <= t) ? se * f3 * wa[i][3] : 0.f;
            *(float4*)(Wsh + t * WPITCH + 4*tx) = wv;
        }
    } else {
        const float4 z = make_float4(0.f, 0.f, 0.f, 0.f);
        #pragma unroll
        for (int i = 0; i < 4; ++i)
            *(float4*)(Wsh + (4*ty + i) * WPITCH + 4*tx) = z;
    }
    // Y1 scaling stays in registers
    #pragma unroll
    for (int i = 0; i < 4; ++i) {
        #pragma unroll
        for (int j = 0; j < 4; ++j) ya[i][j] *= elcv[i];
    }
    __syncthreads();

    // ---- GEMM2: Y += W . x  (causal: s4 <= ty) ----
    for (int s4 = 0; s4 <= ty; ++s4) {
        float4 Wf[4], xf[4];
        #pragma unroll
        for (int i = 0; i < 4; ++i)
            Wf[i] = *(const float4*)(Wsh + (4*ty + i) * WPITCH + 4*s4);
        #pragma unroll
        for (int k = 0; k < 4; ++k)
            xf[k] = *(const float4*)(xsh + (4*s4 + k) * DH + 4*tx);
        #pragma unroll
        for (int i = 0; i < 4; ++i) {
            const float w0 = Wf[i].x, w1 = Wf[i].y, w2 = Wf[i].z, w3 = Wf[i].w;
            ya[i][0] += w0*xf[0].x + w1*xf[1].x + w2*xf[2].x + w3*xf[3].x;
            ya[i][1] += w0*xf[0].y + w1*xf[1].y + w2*xf[2].y + w3*xf[3].y;
            ya[i][2] += w0*xf[0].z + w1*xf[1].z + w2*xf[2].z + w3*xf[3].z;
            ya[i][3] += w0*xf[0].w + w1*xf[1].w + w2*xf[2].w + w3*xf[3].w;
        }
    }
    #pragma unroll
    for (int i = 0; i < 4; ++i) {
        float* yout = out + (rowbase + (size_t)(4*ty + i) * NHD) * DH + 4*tx;
        *(float4*)yout = make_float4(ya[i][0], ya[i][1], ya[i][2], ya[i][3]);
    }
}

// ------------- launch -------------
extern "C" void kernel_launch(void* const* d_in, const int* in_sizes, int n_in,
                              void* d_out, int out_size) {
    const float* x  = (const float*)d_in[0];
    const float* A  = (const float*)d_in[1];
    const float* Bm = (const float*)d_in[2];
    const float* Cm = (const float*)d_in[3];
    const float* dp = (const float*)d_in[4];
    (void)in_sizes; (void)n_in; (void)out_size;

    const int smem1 = (TC*DS + TC*XP1 + 2*TC) * sizeof(float);      // 50.7 KB
    const int smem3 = (2*TC*DS + TC*DS + TC*DH) * sizeof(float);    // 114688 B = 112 KB
    cudaFuncSetAttribute(pass1_kernel, cudaFuncAttributeMaxDynamicSharedMemorySize, smem1);
    cudaFuncSetAttribute(pass3_kernel, cudaFuncAttributeMaxDynamicSharedMemorySize, smem3);

    dim3 grid(NCH, NPAIR);
    pass1_kernel<<<grid, THREADS, smem1>>>(x, Bm, A, dp);
    pass2_kernel<<<dim3(NPAIR, 8), THREADS>>>();
    pass3_kernel<<<grid, THREADS, smem3>>>(x, Bm, Cm, A, dp, (float*)d_out);
}

// round 7
// speedup vs baseline: 1.7255x; 1.7255x over previous
#include <cuda_runtime.h>
#include <cuda_bf16.h>
#include <mma.h>
#include <cstdint>

using namespace nvcuda;

#define BSZ 2
#define LEN 2048
#define NHD 24
#define DH  64
#define DS  128

#define NPAIR (BSZ*NHD)     // 48
#define TC    64
#define NCH   (LEN/TC)      // 32
#define THREADS 256

// ------------- device scratch (no allocation allowed) -------------
__device__ float g_S[NPAIR*NCH*DH*DS];
__device__ float g_H[NPAIR*NCH*DH*DS];
__device__ float g_P[NPAIR*NCH];

__device__ __forceinline__ float neg_sp_abs(float a, float d) {
    float v  = a + d;
    float sp = (v > 20.f) ? v : log1pf(expf(v));
    return -sp * fabsf(a);                          // log(a_bar) <= 0
}

__device__ __forceinline__ void scan_lcp(float* buf, int tid) {
    for (int off = 1; off < TC; off <<= 1) {
        float v = 0.f;
        if (tid < TC && tid >= off) v = buf[tid - off];
        __syncthreads();
        if (tid < TC) buf[tid] += v;
        __syncthreads();
    }
}

// split fp32x4 -> bf16 hi + bf16 lo (packed as uint2 = 4 bf16)
__device__ __forceinline__ void split4(float4 v, uint2& hi, uint2& lo) {
    __nv_bfloat16 h0 = __float2bfloat16(v.x), h1 = __float2bfloat16(v.y);
    __nv_bfloat16 h2 = __float2bfloat16(v.z), h3 = __float2bfloat16(v.w);
    __nv_bfloat16 l0 = __float2bfloat16(v.x - __bfloat162float(h0));
    __nv_bfloat16 l1 = __float2bfloat16(v.y - __bfloat162float(h1));
    __nv_bfloat16 l2 = __float2bfloat16(v.z - __bfloat162float(h2));
    __nv_bfloat16 l3 = __float2bfloat16(v.w - __bfloat162float(h3));
    hi.x = (uint32_t)__bfloat16_as_ushort(h0) | ((uint32_t)__bfloat16_as_ushort(h1) << 16);
    hi.y = (uint32_t)__bfloat16_as_ushort(h2) | ((uint32_t)__bfloat16_as_ushort(h3) << 16);
    lo.x = (uint32_t)__bfloat16_as_ushort(l0) | ((uint32_t)__bfloat16_as_ushort(l1) << 16);
    lo.y = (uint32_t)__bfloat16_as_ushort(l2) | ((uint32_t)__bfloat16_as_ushort(l3) << 16);
}

// =================================================================
// Pass 1 (WMMA): S[d,s] = sum_t (w_t x[t,d]) B[t,s]   (m=64,n=128,k=64)
// =================================================================
#define LDC 136   // bf16 elems per 128-wide row (pad 8)
#define LDX 72    // bf16 elems per 64-wide row  (pad 8)

#define P1_LCP 0
#define P1_LW  256
#define P1_BHI 512
#define P1_BLO (P1_BHI + TC*LDC*2)     // 17920
#define P1_XHI (P1_BLO + TC*LDC*2)     // 35328
#define P1_XLO (P1_XHI + DH*LDX*2)     // 44544
#define SMEM1  (P1_XLO + DH*LDX*2)     // 53760

__global__ __launch_bounds__(THREADS, 2)
void pass1_kernel(const float* __restrict__ x,
                  const float* __restrict__ Bm,
                  const float* __restrict__ A,
                  const float* __restrict__ dp) {
    extern __shared__ __align__(128) char smem[];
    float* lcp = (float*)(smem + P1_LCP);
    float* lw  = (float*)(smem + P1_LW);
    __nv_bfloat16* Bhi = (__nv_bfloat16*)(smem + P1_BHI);
    __nv_bfloat16* Blo = (__nv_bfloat16*)(smem + P1_BLO);
    __nv_bfloat16* Xhi = (__nv_bfloat16*)(smem + P1_XHI);
    __nv_bfloat16* Xlo = (__nv_bfloat16*)(smem + P1_XLO);

    const int tid  = threadIdx.x;
    const int ch   = blockIdx.x;
    const int pair = blockIdx.y;
    const int b    = pair / NHD;
    const int hh   = pair % NHD;
    const size_t rowbase = ((size_t)b * LEN + ch * TC) * NHD + hh;

    if (tid < TC) lcp[tid] = neg_sp_abs(A[rowbase + (size_t)tid * NHD], dp[hh]);
    __syncthreads();
    scan_lcp(lcp, tid);
    if (tid < TC) lw[tid] = __expf(lcp[TC-1] - lcp[tid]);
    if (tid == 0) g_P[pair*NCH + ch] = __expf(lcp[TC-1]);
    __syncthreads();

    // stage B -> bf16 hi/lo [t][s]
    for (int i = tid; i < TC * 32; i += THREADS) {
        int r = i >> 5, c4 = i & 31;
        float4 v = ((const float4*)(Bm + (rowbase + (size_t)r*NHD) * DS))[c4];
        uint2 hi, lo;  split4(v, hi, lo);
        int off = r * (LDC*2) + c4 * 8;
        *(uint2*)(smem + P1_BHI + off) = hi;
        *(uint2*)(smem + P1_BLO + off) = lo;
    }
    // stage x scaled + TRANSPOSED -> [d][t]
    for (int i = tid; i < TC * 16; i += THREADS) {
        int t = i >> 4, c = i & 15;
        float4 v = ((const float4*)(x + (rowbase + (size_t)t*NHD) * DH))[c];
        float wt = lw[t];
        int d0 = 4 * c;
        float vv[4] = {v.x*wt, v.y*wt, v.z*wt, v.w*wt};
        #pragma unroll
        for (int j = 0; j < 4; ++j) {
            __nv_bfloat16 h = __float2bfloat16(vv[j]);
            __nv_bfloat16 l = __float2bfloat16(vv[j] - __bfloat162float(h));
            Xhi[(d0 + j) * LDX + t] = h;
            Xlo[(d0 + j) * LDX + t] = l;
        }
    }
    __syncthreads();

    // WMMA: warp w -> m-tile (w&3), n-tiles (w>>2)*4 .. +3
    const int w  = tid >> 5;
    const int mt = w & 3;
    const int nh = w >> 2;
    wmma::fragment<wmma::accumulator, 16, 16, 16, float> acc[4];
    #pragma unroll
    for (int nt = 0; nt < 4; ++nt) wmma::fill_fragment(acc[nt], 0.f);
    wmma::fragment<wmma::matrix_a, 16, 16, 16, __nv_bfloat16, wmma::row_major> ahi, alo;
    wmma::fragment<wmma::matrix_b, 16, 16, 16, __nv_bfloat16, wmma::row_major> bhi, blo;

    #pragma unroll
    for (int ks = 0; ks < 4; ++ks) {
        wmma::load_matrix_sync(ahi, Xhi + mt*16*LDX + ks*16, LDX);
        wmma::load_matrix_sync(alo, Xlo + mt*16*LDX + ks*16, LDX);
        #pragma unroll
        for (int nt = 0; nt < 4; ++nt) {
            int n0 = nh * 64 + nt * 16;
            wmma::load_matrix_sync(bhi, Bhi + ks*16*LDC + n0, LDC);
            wmma::load_matrix_sync(blo, Blo + ks*16*LDC + n0, LDC);
            wmma::mma_sync(acc[nt], ahi, bhi, acc[nt]);
            wmma::mma_sync(acc[nt], ahi, blo, acc[nt]);
            wmma::mma_sync(acc[nt], alo, bhi, acc[nt]);
        }
    }
    float* Sdst = g_S + ((size_t)(pair*NCH + ch)) * DH * DS;
    #pragma unroll
    for (int nt = 0; nt < 4; ++nt)
        wmma::store_matrix_sync(Sdst + mt*16*DS + nh*64 + nt*16, acc[nt],
                                DS, wmma::mem_row_major);
}

// =================================================================
// Pass 2: pipelined chunk scan (exclusive): H_j stored, H += P*H + S
// =================================================================
__global__ __launch_bounds__(THREADS, 8)
void pass2_kernel() {
    const int pair = blockIdx.x;
    const int idx  = blockIdx.y * THREADS + threadIdx.x;
    const float* Pp = g_P + pair * NCH;
    const size_t base = (size_t)pair * NCH * (DH*DS/4) + idx;

    float4 Hr  = make_float4(0.f, 0.f, 0.f, 0.f);
    float4 nxt = ((const float4*)g_S)[base];
    #pragma unroll 4
    for (int ch = 0; ch < NCH; ++ch) {
        float4 cur = nxt;
        if (ch + 1 < NCH) nxt = ((const float4*)g_S)[base + (size_t)(ch+1)*(DH*DS/4)];
        ((float4*)g_H)[base + (size_t)ch*(DH*DS/4)] = Hr;
        const float P = Pp[ch];
        Hr.x = P*Hr.x + cur.x;  Hr.y = P*Hr.y + cur.y;
        Hr.z = P*Hr.z + cur.z;  Hr.w = P*Hr.w + cur.w;
    }
}

// =================================================================
// Pass 3 (WMMA): R[t, j] = C . [B;H]^T  (m=64, n=128, k=128)
//   j<64 -> W (decay+mask in smem), j>=64 -> Y1 (scale exp(lcp_t))
//   then Y = Y1 + W.x  (fp32 CUDA core, causal)
// =================================================================
#define P3_LCP  0
#define P3_GLA  256
#define P3_GINV 512
#define P3_ELC  768
#define P3_CHI  1024
#define P3_CLO  (P3_CHI + TC*LDC*2)      // 18432
#define P3_DHI  (P3_CLO + TC*LDC*2)      // 35840
#define P3_DLO  (P3_DHI + 2*TC*LDC*2)    // 70656
#define SMEM3   (P3_DLO + 2*TC*LDC*2)    // 105472
#define P3_W    P3_DHI                   // fp32 64 x 68 (aliases Dhi)
#define P3_Y    (P3_DHI + TC*68*4)       // fp32 64 x 68
#define P3_X    P3_CHI                   // fp32 64 x 64 (aliases Chi)
#define LDW 68

__global__ __launch_bounds__(THREADS, 2)
void pass3_kernel(const float* __restrict__ x,
                  const float* __restrict__ Bm,
                  const float* __restrict__ Cm,
                  const float* __restrict__ A,
                  const float* __restrict__ dp,
                  float* __restrict__ out) {
    extern __shared__ __align__(128) char smem[];
    float* lcp  = (float*)(smem + P3_LCP);
    float* gla  = (float*)(smem + P3_GLA);
    float* ginv = (float*)(smem + P3_GINV);
    float* elc  = (float*)(smem + P3_ELC);
    float* Wsh  = (float*)(smem + P3_W);
    float* Ysh  = (float*)(smem + P3_Y);
    float* xs   = (float*)(smem + P3_X);

    const int tid  = threadIdx.x;
    const int ch   = blockIdx.x;
    const int pair = blockIdx.y;
    const int b    = pair / NHD;
    const int hh   = pair % NHD;
    const size_t rowbase = ((size_t)b * LEN + ch * TC) * NHD + hh;

    if (tid < TC) {
        float la = neg_sp_abs(A[rowbase + (size_t)tid * NHD], dp[hh]);
        gla[tid] = la;
        lcp[tid] = la;
    }
    __syncthreads();
    scan_lcp(lcp, tid);
    if (tid < TC) {
        elc[tid]  = __expf(lcp[tid]);
        ginv[tid] = fminf(__expf(-gla[tid]), 1e30f);
    }

    // stage C -> Chi/Clo [t][k]
    for (int i = tid; i < TC * 32; i += THREADS) {
        int r = i >> 5, c4 = i & 31;
        float4 v = ((const float4*)(Cm + (rowbase + (size_t)r*NHD) * DS))[c4];
        uint2 hi, lo;  split4(v, hi, lo);
        int off = r * (LDC*2) + c4 * 8;
        *(uint2*)(smem + P3_CHI + off) = hi;
        *(uint2*)(smem + P3_CLO + off) = lo;
    }
    // stage D=[B;H] -> Dhi/Dlo [j][k]
    const float* Hsrc = g_H + ((size_t)(pair*NCH + ch)) * DH * DS;
    for (int i = tid; i < 2 * TC * 32; i += THREADS) {
        int r = i >> 5, c4 = i & 31;
        float4 v = (r < 64)
            ? ((const float4*)(Bm + (rowbase + (size_t)r*NHD) * DS))[c4]
            : ((const float4*)(Hsrc + (size_t)(r - 64) * DS))[c4];
        uint2 hi, lo;  split4(v, hi, lo);
        int off = r * (LDC*2) + c4 * 8;
        *(uint2*)(smem + P3_DHI + off) = hi;
        *(uint2*)(smem + P3_DLO + off) = lo;
    }
    // preload x into registers (dumped to smem after GEMM1)
    float4 xr[4];
    #pragma unroll
    for (int j = 0; j < 4; ++j) {
        int i = tid + j * THREADS;          // float4 idx in 64x64
        int t = i >> 4, c = i & 15;
        xr[j] = ((const float4*)(x + (rowbase + (size_t)t*NHD) * DH))[c];
    }
    __syncthreads();

    // ---- GEMM1 (WMMA, 3-pass bf16 split) ----
    {
        const int w  = tid >> 5;
        const int mt = w & 3;     // t-tile
        const int nh = w >> 2;    // 0 -> W cols, 1 -> Y cols
        const __nv_bfloat16* Cb = (const __nv_bfloat16*)(smem + P3_CHI);
        const __nv_bfloat16* Cl = (const __nv_bfloat16*)(smem + P3_CLO);
        const __nv_bfloat16* Db = (const __nv_bfloat16*)(smem + P3_DHI);
        const __nv_bfloat16* Dl = (const __nv_bfloat16*)(smem + P3_DLO);

        wmma::fragment<wmma::accumulator, 16, 16, 16, float> acc[4];
        #pragma unroll
        for (int nt = 0; nt < 4; ++nt) wmma::fill_fragment(acc[nt], 0.f);
        wmma::fragment<wmma::matrix_a, 16, 16, 16, __nv_bfloat16, wmma::row_major> ahi, alo;
        wmma::fragment<wmma::matrix_b, 16, 16, 16, __nv_bfloat16, wmma::col_major> bhi, blo;

        #pragma unroll
        for (int ks = 0; ks < 8; ++ks) {
            wmma::load_matrix_sync(ahi, Cb + mt*16*LDC + ks*16, LDC);
            wmma::load_matrix_sync(alo, Cl + mt*16*LDC + ks*16, LDC);
            #pragma unroll
            for (int nt = 0; nt < 4; ++nt) {
                int j0 = nh * 64 + nt * 16;
                wmma::load_matrix_sync(bhi, Db + j0*LDC + ks*16, LDC);
                wmma::load_matrix_sync(blo, Dl + j0*LDC + ks*16, LDC);
                wmma::mma_sync(acc[nt], ahi, bhi, acc[nt]);
                wmma::mma_sync(acc[nt], ahi, blo, acc[nt]);
                wmma::mma_sync(acc[nt], alo, bhi, acc[nt]);
            }
        }
        __syncthreads();   // all warps done reading C/D before aliasing writes

        float* dst = (nh == 0) ? Wsh : Ysh;
        #pragma unroll
        for (int nt = 0; nt < 4; ++nt)
            wmma::store_matrix_sync(dst + mt*16*LDW + nt*16, acc[nt],
                                    LDW, wmma::mem_row_major);
    }
    // dump x registers into smem (aliases Chi region)
    #pragma unroll
    for (int j = 0; j < 4; ++j) ((float4*)xs)[tid + j * THREADS] = xr[j];
    __syncthreads();

    // ---- epilogue: decay/mask W, scale Y ----
    {
        const int t  = tid >> 2;
        const int s0 = (tid & 3) * 16;
        float f = (s0 <= t) ? __expf(lcp[t] - lcp[s0]) : 0.f;
        float* wr = Wsh + t * LDW + s0;
        float* yr = Ysh + t * LDW + s0;
        const float et = elc[t];
        #pragma unroll
        for (int i2 = 0; i2 < 16; ++i2) {
            int s = s0 + i2;
            if (i2) f *= ginv[s];           // advance exp(lcp_t - lcp_s)
            wr[i2] = (s <= t) ? f * wr[i2] : 0.f;
            yr[i2] = et * yr[i2];
        }
    }
    __syncthreads();

    // ---- GEMM2: Y = Y1 + W . x  (causal), fp32 ----
    const int ty = tid >> 4, tx = tid & 15;
    float ya[4][4];
    #pragma unroll
    for (int i = 0; i < 4; ++i) {
        float4 yv = *(const float4*)(Ysh + (4*ty + i) * LDW + 4*tx);
        ya[i][0] = yv.x; ya[i][1] = yv.y; ya[i][2] = yv.z; ya[i][3] = yv.w;
    }
    for (int s4 = 0; s4 <= ty; ++s4) {
        float4 Wf[4], xf[4];
        #pragma unroll
        for (int i = 0; i < 4; ++i)
            Wf[i] = *(const float4*)(Wsh + (4*ty + i) * LDW + 4*s4);
        #pragma unroll
        for (int k = 0; k < 4; ++k)
            xf[k] = *(const float4*)(xs + (4*s4 + k) * DH + 4*tx);
        #pragma unroll
        for (int i = 0; i < 4; ++i) {
            const float w0 = Wf[i].x, w1 = Wf[i].y, w2 = Wf[i].z, w3 = Wf[i].w;
            ya[i][0] += w0*xf[0].x + w1*xf[1].x + w2*xf[2].x + w3*xf[3].x;
            ya[i][1] += w0*xf[0].y + w1*xf[1].y + w2*xf[2].y + w3*xf[3].y;
            ya[i][2] += w0*xf[0].z + w1*xf[1].z + w2*xf[2].z + w3*xf[3].z;
            ya[i][3] += w0*xf[0].w + w1*xf[1].w + w2*xf[2].w + w3*xf[3].w;
        }
    }
    #pragma unroll
    for (int i = 0; i < 4; ++i) {
        float* yout = out + (rowbase + (size_t)(4*ty + i) * NHD) * DH + 4*tx;
        *(float4*)yout = make_float4(ya[i][0], ya[i][1], ya[i][2], ya[i][3]);
    }
}

// ------------- launch -------------
extern "C" void kernel_launch(void* const* d_in, const int* in_sizes, int n_in,
                              void* d_out, int out_size) {
    const float* x  = (const float*)d_in[0];
    const float* A  = (const float*)d_in[1];
    const float* Bm = (const float*)d_in[2];
    const float* Cm = (const float*)d_in[3];
    const float* dp = (const float*)d_in[4];
    (void)in_sizes; (void)n_in; (void)out_size;

    cudaFuncSetAttribute(pass1_kernel, cudaFuncAttributeMaxDynamicSharedMemorySize, SMEM1);
    cudaFuncSetAttribute(pass3_kernel, cudaFuncAttributeMaxDynamicSharedMemorySize, SMEM3);

    dim3 grid(NCH, NPAIR);
    pass1_kernel<<<grid, THREADS, SMEM1>>>(x, Bm, A, dp);
    pass2_kernel<<<dim3(NPAIR, 8), THREADS>>>();
    pass3_kernel<<<grid, THREADS, SMEM3>>>(x, Bm, Cm, A, dp, (float*)d_out);
}

// round 11
// speedup vs baseline: 1.8956x; 1.0986x over previous
#include <cuda_runtime.h>
#include <cuda_bf16.h>
#include <mma.h>
#include <cstdint>

using namespace nvcuda;

#define BSZ 2
#define LEN 2048
#define NHD 24
#define DH  64
#define DS  128

#define NPAIR (BSZ*NHD)     // 48
#define TC    64
#define NCH   (LEN/TC)      // 32
#define THREADS 256

#define LDC 136   // bf16 row pitch for 128-wide rows
#define LDX 72    // bf16 row pitch for 64-wide rows
#define LDH 72
#define LDW 68    // fp32 row pitch for W/Y

// ------------- device scratch (no allocation allowed) -------------
__device__ float         g_S  [NPAIR*NCH*DH*DS];   // [s][d] per chunk
__device__ __nv_bfloat16 g_Hhi[NPAIR*NCH*DH*DS];   // [s][d], bf16 hi
__device__ __nv_bfloat16 g_Hlo[NPAIR*NCH*DH*DS];   // [s][d], bf16 lo
__device__ float         g_P  [NPAIR*NCH];

__device__ __forceinline__ float neg_sp_abs(float a, float d) {
    float v  = a + d;
    float sp = (v > 20.f) ? v : log1pf(expf(v));
    return -sp * fabsf(a);                          // log(a_bar) <= 0
}

// 2-barrier inclusive scan of buf[0..63]
__device__ __forceinline__ void scan64(float* buf, int tid) {
    if (tid < 64) {
        float v = buf[tid];
        #pragma unroll
        for (int o = 1; o < 32; o <<= 1) {
            float u = __shfl_up_sync(0xffffffffu, v, o);
            if ((tid & 31) >= o) v += u;
        }
        buf[tid] = v;
    }
    __syncthreads();
    if (tid >= 32 && tid < 64) buf[tid] += buf[31];
    __syncthreads();
}

__device__ __forceinline__ void split4(float4 v, uint2& hi, uint2& lo) {
    __nv_bfloat16 h0 = __float2bfloat16(v.x), h1 = __float2bfloat16(v.y);
    __nv_bfloat16 h2 = __float2bfloat16(v.z), h3 = __float2bfloat16(v.w);
    __nv_bfloat16 l0 = __float2bfloat16(v.x - __bfloat162float(h0));
    __nv_bfloat16 l1 = __float2bfloat16(v.y - __bfloat162float(h1));
    __nv_bfloat16 l2 = __float2bfloat16(v.z - __bfloat162float(h2));
    __nv_bfloat16 l3 = __float2bfloat16(v.w - __bfloat162float(h3));
    hi.x = (uint32_t)__bfloat16_as_ushort(h0) | ((uint32_t)__bfloat16_as_ushort(h1) << 16);
    hi.y = (uint32_t)__bfloat16_as_ushort(h2) | ((uint32_t)__bfloat16_as_ushort(h3) << 16);
    lo.x = (uint32_t)__bfloat16_as_ushort(l0) | ((uint32_t)__bfloat16_as_ushort(l1) << 16);
    lo.y = (uint32_t)__bfloat16_as_ushort(l2) | ((uint32_t)__bfloat16_as_ushort(l3) << 16);
}

// =================================================================
// Pass 1 (WMMA, transpose-free): S'[s,d] = sum_t B[t,s] (w_t x[t,d])
//   matrix_a = B tile [t][s] as col_major; matrix_b = Xw [t][d] row_major
// =================================================================
#define P1_LCP 0
#define P1_LW  256
#define P1_BHI 512
#define P1_BLO (P1_BHI + TC*LDC*2)     // +17408
#define P1_XHI (P1_BLO + TC*LDC*2)
#define P1_XLO (P1_XHI + TC*LDX*2)     // +9216
#define SMEM1  (P1_XLO + TC*LDX*2)     // 53760

__global__ __launch_bounds__(THREADS, 2)
void pass1_kernel(const float* __restrict__ x,
                  const float* __restrict__ Bm,
                  const float* __restrict__ A,
                  const float* __restrict__ dp) {
    extern __shared__ __align__(128) char smem[];
    float* lcp = (float*)(smem + P1_LCP);
    float* lw  = (float*)(smem + P1_LW);
    const __nv_bfloat16* Bhi = (const __nv_bfloat16*)(smem + P1_BHI);
    const __nv_bfloat16* Blo = (const __nv_bfloat16*)(smem + P1_BLO);
    const __nv_bfloat16* Xhi = (const __nv_bfloat16*)(smem + P1_XHI);
    const __nv_bfloat16* Xlo = (const __nv_bfloat16*)(smem + P1_XLO);

    const int tid  = threadIdx.x;
    const int ch   = blockIdx.x;
    const int pair = blockIdx.y;
    const int b    = pair / NHD;
    const int hh   = pair % NHD;
    const size_t rowbase = ((size_t)b * LEN + ch * TC) * NHD + hh;

    if (tid < TC) lcp[tid] = neg_sp_abs(A[rowbase + (size_t)tid * NHD], dp[hh]);
    __syncthreads();
    scan64(lcp, tid);
    if (tid < TC) lw[tid] = __expf(lcp[TC-1] - lcp[tid]);
    if (tid == 0) g_P[pair*NCH + ch] = __expf(lcp[TC-1]);
    __syncthreads();

    // stage B [t][s] bf16 hi/lo
    for (int i = tid; i < TC * 32; i += THREADS) {
        int t = i >> 5, c4 = i & 31;
        float4 v = ((const float4*)(Bm + (rowbase + (size_t)t*NHD) * DS))[c4];
        uint2 hi, lo;  split4(v, hi, lo);
        int off = t * (LDC*2) + c4 * 8;
        *(uint2*)(smem + P1_BHI + off) = hi;
        *(uint2*)(smem + P1_BLO + off) = lo;
    }
    // stage x scaled [t][d] bf16 hi/lo (no transpose)
    for (int i = tid; i < TC * 16; i += THREADS) {
        int t = i >> 4, c = i & 15;
        float4 v = ((const float4*)(x + (rowbase + (size_t)t*NHD) * DH))[c];
        float wt = lw[t];
        v.x *= wt; v.y *= wt; v.z *= wt; v.w *= wt;
        uint2 hi, lo;  split4(v, hi, lo);
        int off = t * (LDX*2) + c * 8;
        *(uint2*)(smem + P1_XHI + off) = hi;
        *(uint2*)(smem + P1_XLO + off) = lo;
    }
    __syncthreads();

    // WMMA: warp w owns m-tile (s) = w, n-tiles (d) 0..3
    const int w = tid >> 5;
    wmma::fragment<wmma::accumulator, 16, 16, 16, float> acc[4];
    #pragma unroll
    for (int nt = 0; nt < 4; ++nt) wmma::fill_fragment(acc[nt], 0.f);
    wmma::fragment<wmma::matrix_a, 16, 16, 16, __nv_bfloat16, wmma::col_major> ahi, alo;
    wmma::fragment<wmma::matrix_b, 16, 16, 16, __nv_bfloat16, wmma::row_major> bhi, blo;

    #pragma unroll
    for (int ks = 0; ks < 4; ++ks) {
        wmma::load_matrix_sync(ahi, Bhi + ks*16*LDC + w*16, LDC);
        wmma::load_matrix_sync(alo, Blo + ks*16*LDC + w*16, LDC);
        #pragma unroll
        for (int nt = 0; nt < 4; ++nt) {
            wmma::load_matrix_sync(bhi, Xhi + ks*16*LDX + nt*16, LDX);
            wmma::load_matrix_sync(blo, Xlo + ks*16*LDX + nt*16, LDX);
            wmma::mma_sync(acc[nt], ahi, bhi, acc[nt]);
            wmma::mma_sync(acc[nt], ahi, blo, acc[nt]);
            wmma::mma_sync(acc[nt], alo, bhi, acc[nt]);
        }
    }
    float* Sdst = g_S + ((size_t)(pair*NCH + ch)) * DH * DS;   // [s][d]
    #pragma unroll
    for (int nt = 0; nt < 4; ++nt)
        wmma::store_matrix_sync(Sdst + w*16*DH + nt*16, acc[nt],
                                DH, wmma::mem_row_major);
}

// =================================================================
// Pass 2: exclusive chunk scan; H written pre-split as bf16 hi/lo
// =================================================================
__global__ __launch_bounds__(THREADS, 8)
void pass2_kernel() {
    const int pair = blockIdx.x;
    const int idx  = blockIdx.y * THREADS + threadIdx.x;   // float4/uint2 idx
    const float* Pp = g_P + pair * NCH;
    const size_t base = (size_t)pair * NCH * 2048 + idx;

    float4 Hr  = make_float4(0.f, 0.f, 0.f, 0.f);
    float4 nxt = ((const float4*)g_S)[base];
    #pragma unroll 4
    for (int ch = 0; ch < NCH; ++ch) {
        float4 cur = nxt;
        if (ch + 1 < NCH) nxt = ((const float4*)g_S)[base + (size_t)(ch+1)*2048];
        uint2 hi, lo;  split4(Hr, hi, lo);
        ((uint2*)g_Hhi)[base + (size_t)ch*2048] = hi;
        ((uint2*)g_Hlo)[base + (size_t)ch*2048] = lo;
        const float P = Pp[ch];
        Hr.x = P*Hr.x + cur.x;  Hr.y = P*Hr.y + cur.y;
        Hr.z = P*Hr.z + cur.z;  Hr.w = P*Hr.w + cur.w;
    }
}

// =================================================================
// Pass 3 (WMMA):
//   W-warps (0-3): W[t,s'] = C . B^T  (causal tile skip)
//   Y-warps (4-7): Y1[t,d] = C . H'[s][d]  (H' row-major, no transpose)
//   epilogue decay/mask; GEMM2 fp32: Y = Y1 + W . x
// =================================================================
#define P3_LCP  0
#define P3_GINV 256
#define P3_ELC  512
#define P3_CHI  1024
#define P3_CLO  (P3_CHI + TC*LDC*2)      // +17408
#define P3_BHI  (P3_CLO + TC*LDC*2)
#define P3_BLO  (P3_BHI + TC*LDC*2)
#define P3_HHI  (P3_BLO + TC*LDC*2)
#define P3_HLO  (P3_HHI + 2*TC*LDH*2)    // +18432
#define SMEM3   (P3_HLO + 2*TC*LDH*2)    // 107520
#define P3_W    P3_BHI                   // fp32 64 x 68 (17408 B, aliases Bhi)
#define P3_Y    P3_BLO                   // fp32 64 x 68 (aliases Blo)
#define P3_X    P3_CHI                   // fp32 64 x 64 (aliases Chi)

__global__ __launch_bounds__(THREADS, 2)
void pass3_kernel(const float* __restrict__ x,
                  const float* __restrict__ Bm,
                  const float* __restrict__ Cm,
                  const float* __restrict__ A,
                  const float* __restrict__ dp,
                  float* __restrict__ out) {
    extern __shared__ __align__(128) char smem[];
    float* lcp  = (float*)(smem + P3_LCP);
    float* ginv = (float*)(smem + P3_GINV);
    float* elc  = (float*)(smem + P3_ELC);
    float* Wsh  = (float*)(smem + P3_W);
    float* Ysh  = (float*)(smem + P3_Y);
    float* xs   = (float*)(smem + P3_X);

    const int tid  = threadIdx.x;
    const int ch   = blockIdx.x;
    const int pair = blockIdx.y;
    const int b    = pair / NHD;
    const int hh   = pair % NHD;
    const size_t rowbase = ((size_t)b * LEN + ch * TC) * NHD + hh;

    if (tid < TC) {
        float la = neg_sp_abs(A[rowbase + (size_t)tid * NHD], dp[hh]);
        lcp[tid]  = la;
        ginv[tid] = fminf(__expf(-la), 1e30f);
    }
    __syncthreads();
    scan64(lcp, tid);
    if (tid < TC) elc[tid] = __expf(lcp[tid]);

    // stage C and B [t][k] bf16 hi/lo
    for (int i = tid; i < TC * 32; i += THREADS) {
        int t = i >> 5, c4 = i & 31;
        float4 vc = ((const float4*)(Cm + (rowbase + (size_t)t*NHD) * DS))[c4];
        float4 vb = ((const float4*)(Bm + (rowbase + (size_t)t*NHD) * DS))[c4];
        uint2 hi, lo;
        int off = t * (LDC*2) + c4 * 8;
        split4(vc, hi, lo);
        *(uint2*)(smem + P3_CHI + off) = hi;
        *(uint2*)(smem + P3_CLO + off) = lo;
        split4(vb, hi, lo);
        *(uint2*)(smem + P3_BHI + off) = hi;
        *(uint2*)(smem + P3_BLO + off) = lo;
    }
    // stage H (pure copy of pre-split bf16) [s][d]
    {
        const uint2* Hh4 = (const uint2*)g_Hhi + (size_t)(pair*NCH + ch) * 2048;
        const uint2* Hl4 = (const uint2*)g_Hlo + (size_t)(pair*NCH + ch) * 2048;
        for (int i = tid; i < 2048; i += THREADS) {
            int s = i >> 4, c = i & 15;
            int off = s * (LDH*2) + c * 8;
            *(uint2*)(smem + P3_HHI + off) = Hh4[i];
            *(uint2*)(smem + P3_HLO + off) = Hl4[i];
        }
    }
    // preload x into registers (dumped post-GEMM1 over Chi)
    float4 xr[4];
    #pragma unroll
    for (int j = 0; j < 4; ++j) {
        int i = tid + j * THREADS;
        int t = i >> 4, c = i & 15;
        xr[j] = ((const float4*)(x + (rowbase + (size_t)t*NHD) * DH))[c];
    }
    __syncthreads();

    // ---- GEMM1 ----
    const int w = tid >> 5;
    wmma::fragment<wmma::accumulator, 16, 16, 16, float> acc[4];
    #pragma unroll
    for (int nt = 0; nt < 4; ++nt) wmma::fill_fragment(acc[nt], 0.f);
    {
        wmma::fragment<wmma::matrix_a, 16, 16, 16, __nv_bfloat16, wmma::row_major> ahi, alo;
        const __nv_bfloat16* Cb = (const __nv_bfloat16*)(smem + P3_CHI);
        const __nv_bfloat16* Cl = (const __nv_bfloat16*)(smem + P3_CLO);
        if (w < 4) {   // W = C . B^T   (causal skip: nt > mt -> zero tile)
            const __nv_bfloat16* Db = (const __nv_bfloat16*)(smem + P3_BHI);
            const __nv_bfloat16* Dl = (const __nv_bfloat16*)(smem + P3_BLO);
            wmma::fragment<wmma::matrix_b, 16, 16, 16, __nv_bfloat16, wmma::col_major> bhi, blo;
            #pragma unroll
            for (int ks = 0; ks < 8; ++ks) {
                wmma::load_matrix_sync(ahi, Cb + w*16*LDC + ks*16, LDC);
                wmma::load_matrix_sync(alo, Cl + w*16*LDC + ks*16, LDC);
                #pragma unroll
                for (int nt = 0; nt < 4; ++nt) {
                    if (nt > w) break;
                    wmma::load_matrix_sync(bhi, Db + nt*16*LDC + ks*16, LDC);
                    wmma::load_matrix_sync(blo, Dl + nt*16*LDC + ks*16, LDC);
                    wmma::mma_sync(acc[nt], ahi, bhi, acc[nt]);
                    wmma::mma_sync(acc[nt], ahi, blo, acc[nt]);
                    wmma::mma_sync(acc[nt], alo, bhi, acc[nt]);
                }
            }
        } else {       // Y1 = C . H'  (H' row-major [s][d])
            const int mt = w - 4;
            const __nv_bfloat16* Hb = (const __nv_bfloat16*)(smem + P3_HHI);
            const __nv_bfloat16* Hl = (const __nv_bfloat16*)(smem + P3_HLO);
            wmma::fragment<wmma::matrix_b, 16, 16, 16, __nv_bfloat16, wmma::row_major> bhi, blo;
            #pragma unroll
            for (int ks = 0; ks < 8; ++ks) {
                wmma::load_matrix_sync(ahi, Cb + mt*16*LDC + ks*16, LDC);
                wmma::load_matrix_sync(alo, Cl + mt*16*LDC + ks*16, LDC);
                #pragma unroll
                for (int nt = 0; nt < 4; ++nt) {
                    wmma::load_matrix_sync(bhi, Hb + ks*16*LDH + nt*16, LDH);
                    wmma::load_matrix_sync(blo, Hl + ks*16*LDH + nt*16, LDH);
                    wmma::mma_sync(acc[nt], ahi, bhi, acc[nt]);
                    wmma::mma_sync(acc[nt], ahi, blo, acc[nt]);
                    wmma::mma_sync(acc[nt], alo, bhi, acc[nt]);
                }
            }
        }
    }
    __syncthreads();   // all reads of C/B/H done before aliasing stores

    if (w < 4) {
        #pragma unroll
        for (int nt = 0; nt < 4; ++nt) {
            if (nt > w) break;
            wmma::store_matrix_sync(Wsh + w*16*LDW + nt*16, acc[nt],
                                    LDW, wmma::mem_row_major);
        }
    } else {
        #pragma unroll
        for (int nt = 0; nt < 4; ++nt)
            wmma::store_matrix_sync(Ysh + (w-4)*16*LDW + nt*16, acc[nt],
                                    LDW, wmma::mem_row_major);
    }
    #pragma unroll
    for (int j = 0; j < 4; ++j) ((float4*)xs)[tid + j * THREADS] = xr[j];
    __syncthreads();

    // ---- epilogue: decay/mask W, scale Y1 ----
    {
        const int t  = tid >> 2;
        const int s0 = (tid & 3) * 16;
        float f = (s0 <= t) ? __expf(lcp[t] - lcp[s0]) : 0.f;
        float* wr = Wsh + t * LDW + s0;
        float* yr = Ysh + t * LDW + s0;
        const float et = elc[t];
        #pragma unroll
        for (int i2 = 0; i2 < 16; ++i2) {
            int s = s0 + i2;
            if (i2) f *= ginv[s];
            wr[i2] = (s <= t) ? f * wr[i2] : 0.f;
            yr[i2] = et * yr[i2];
        }
    }
    __syncthreads();

    // ---- GEMM2: Y = Y1 + W . x  (causal, fp32) ----
    const int ty = tid >> 4, tx = tid & 15;
    float ya[4][4];
    #pragma unroll
    for (int i = 0; i < 4; ++i) {
        float4 yv = *(const float4*)(Ysh + (4*ty + i) * LDW + 4*tx);
        ya[i][0] = yv.x; ya[i][1] = yv.y; ya[i][2] = yv.z; ya[i][3] = yv.w;
    }
    for (int s4 = 0; s4 <= ty; ++s4) {
        float4 Wf[4], xf[4];
        #pragma unroll
        for (int i = 0; i < 4; ++i)
            Wf[i] = *(const float4*)(Wsh + (4*ty + i) * LDW + 4*s4);
        #pragma unroll
        for (int k = 0; k < 4; ++k)
            xf[k] = *(const float4*)(xs + (4*s4 + k) * DH + 4*tx);
        #pragma unroll
        for (int i = 0; i < 4; ++i) {
            const float w0 = Wf[i].x, w1 = Wf[i].y, w2 = Wf[i].z, w3 = Wf[i].w;
            ya[i][0] += w0*xf[0].x + w1*xf[1].x + w2*xf[2].x + w3*xf[3].x;
            ya[i][1] += w0*xf[0].y + w1*xf[1].y + w2*xf[2].y + w3*xf[3].y;
            ya[i][2] += w0*xf[0].z + w1*xf[1].z + w2*xf[2].z + w3*xf[3].z;
            ya[i][3] += w0*xf[0].w + w1*xf[1].w + w2*xf[2].w + w3*xf[3].w;
        }
    }
    #pragma unroll
    for (int i = 0; i < 4; ++i) {
        float* yout = out + (rowbase + (size_t)(4*ty + i) * NHD) * DH + 4*tx;
        *(float4*)yout = make_float4(ya[i][0], ya[i][1], ya[i][2], ya[i][3]);
    }
}

// ------------- launch -------------
extern "C" void kernel_launch(void* const* d_in, const int* in_sizes, int n_in,
                              void* d_out, int out_size) {
    const float* x  = (const float*)d_in[0];
    const float* A  = (const float*)d_in[1];
    const float* Bm = (const float*)d_in[2];
    const float* Cm = (const float*)d_in[3];
    const float* dp = (const float*)d_in[4];
    (void)in_sizes; (void)n_in; (void)out_size;

    cudaFuncSetAttribute(pass1_kernel, cudaFuncAttributeMaxDynamicSharedMemorySize, SMEM1);
    cudaFuncSetAttribute(pass3_kernel, cudaFuncAttributeMaxDynamicSharedMemorySize, SMEM3);

    dim3 grid(NCH, NPAIR);
    pass1_kernel<<<grid, THREADS, SMEM1>>>(x, Bm, A, dp);
    pass2_kernel<<<dim3(NPAIR, 8), THREADS>>>();
    pass3_kernel<<<grid, THREADS, SMEM3>>>(x, Bm, Cm, A, dp, (float*)d_out);
}

// round 12
// speedup vs baseline: 2.1114x; 1.1138x over previous
#include <cuda_runtime.h>
#include <cuda_bf16.h>
#include <mma.h>
#include <cstdint>

using namespace nvcuda;

#define BSZ 2
#define LEN 2048
#define NHD 24
#define DH  64
#define DS  128

#define NPAIR (BSZ*NHD)     // 48
#define TC    64
#define NCH   (LEN/TC)      // 32
#define THREADS 256

#define LDC 136   // bf16 row pitch for 128-wide rows
#define LDX 72    // bf16 row pitch for 64-wide rows
#define LDH 72
#define LDW 68    // fp32 row pitch for W/Y

// ------------- device scratch (no allocation allowed) -------------
__device__ float         g_S  [NPAIR*NCH*DH*DS];   // [s][d] per chunk
__device__ __nv_bfloat16 g_Hhi[NPAIR*NCH*DH*DS];   // [s][d], bf16 hi
__device__ __nv_bfloat16 g_Hlo[NPAIR*NCH*DH*DS];   // [s][d], bf16 lo
__device__ float         g_P  [NPAIR*NCH];

__device__ __forceinline__ float neg_sp_abs(float a, float d) {
    float v  = a + d;
    float sp = (v > 20.f) ? v : log1pf(expf(v));
    return -sp * fabsf(a);                          // log(a_bar) <= 0
}

// 2-barrier inclusive scan of buf[0..63]
__device__ __forceinline__ void scan64(float* buf, int tid) {
    if (tid < 64) {
        float v = buf[tid];
        #pragma unroll
        for (int o = 1; o < 32; o <<= 1) {
            float u = __shfl_up_sync(0xffffffffu, v, o);
            if ((tid & 31) >= o) v += u;
        }
        buf[tid] = v;
    }
    __syncthreads();
    if (tid >= 32 && tid < 64) buf[tid] += buf[31];
    __syncthreads();
}

__device__ __forceinline__ void split4(float4 v, uint2& hi, uint2& lo) {
    __nv_bfloat16 h0 = __float2bfloat16(v.x), h1 = __float2bfloat16(v.y);
    __nv_bfloat16 h2 = __float2bfloat16(v.z), h3 = __float2bfloat16(v.w);
    __nv_bfloat16 l0 = __float2bfloat16(v.x - __bfloat162float(h0));
    __nv_bfloat16 l1 = __float2bfloat16(v.y - __bfloat162float(h1));
    __nv_bfloat16 l2 = __float2bfloat16(v.z - __bfloat162float(h2));
    __nv_bfloat16 l3 = __float2bfloat16(v.w - __bfloat162float(h3));
    hi.x = (uint32_t)__bfloat16_as_ushort(h0) | ((uint32_t)__bfloat16_as_ushort(h1) << 16);
    hi.y = (uint32_t)__bfloat16_as_ushort(h2) | ((uint32_t)__bfloat16_as_ushort(h3) << 16);
    lo.x = (uint32_t)__bfloat16_as_ushort(l0) | ((uint32_t)__bfloat16_as_ushort(l1) << 16);
    lo.y = (uint32_t)__bfloat16_as_ushort(l2) | ((uint32_t)__bfloat16_as_ushort(l3) << 16);
}

__device__ __forceinline__ unsigned smem_u32(const void* p) {
    return (unsigned)__cvta_generic_to_shared(p);
}
__device__ __forceinline__ void cpa16(unsigned dst, const void* src) {
    asm volatile("cp.async.cg.shared.global [%0], [%1], 16;\n" :: "r"(dst), "l"(src));
}

// =================================================================
// Pass 1 (WMMA, transpose-free): S'[s,d] = sum_t B[t,s] (w_t x[t,d])
// 3 CTAs/SM (register cap 84) for latency hiding.
// =================================================================
#define P1_LCP 0
#define P1_LW  256
#define P1_BHI 512
#define P1_BLO (P1_BHI + TC*LDC*2)
#define P1_XHI (P1_BLO + TC*LDC*2)
#define P1_XLO (P1_XHI + TC*LDX*2)
#define SMEM1  (P1_XLO + TC*LDX*2)     // 53760

__global__ __launch_bounds__(THREADS, 3)
void pass1_kernel(const float* __restrict__ x,
                  const float* __restrict__ Bm,
                  const float* __restrict__ A,
                  const float* __restrict__ dp) {
    extern __shared__ __align__(128) char smem[];
    float* lcp = (float*)(smem + P1_LCP);
    float* lw  = (float*)(smem + P1_LW);
    const __nv_bfloat16* Bhi = (const __nv_bfloat16*)(smem + P1_BHI);
    const __nv_bfloat16* Blo = (const __nv_bfloat16*)(smem + P1_BLO);
    const __nv_bfloat16* Xhi = (const __nv_bfloat16*)(smem + P1_XHI);
    const __nv_bfloat16* Xlo = (const __nv_bfloat16*)(smem + P1_XLO);

    const int tid  = threadIdx.x;
    const int ch   = blockIdx.x;
    const int pair = blockIdx.y;
    const int b    = pair / NHD;
    const int hh   = pair % NHD;
    const size_t rowbase = ((size_t)b * LEN + ch * TC) * NHD + hh;

    if (tid < TC) lcp[tid] = neg_sp_abs(A[rowbase + (size_t)tid * NHD], dp[hh]);
    __syncthreads();
    scan64(lcp, tid);
    if (tid < TC) lw[tid] = __expf(lcp[TC-1] - lcp[tid]);
    if (tid == 0) g_P[pair*NCH + ch] = __expf(lcp[TC-1]);
    __syncthreads();

    // stage B [t][s] bf16 hi/lo
    for (int i = tid; i < TC * 32; i += THREADS) {
        int t = i >> 5, c4 = i & 31;
        float4 v = ((const float4*)(Bm + (rowbase + (size_t)t*NHD) * DS))[c4];
        uint2 hi, lo;  split4(v, hi, lo);
        int off = t * (LDC*2) + c4 * 8;
        *(uint2*)(smem + P1_BHI + off) = hi;
        *(uint2*)(smem + P1_BLO + off) = lo;
    }
    // stage x scaled [t][d] bf16 hi/lo
    for (int i = tid; i < TC * 16; i += THREADS) {
        int t = i >> 4, c = i & 15;
        float4 v = ((const float4*)(x + (rowbase + (size_t)t*NHD) * DH))[c];
        float wt = lw[t];
        v.x *= wt; v.y *= wt; v.z *= wt; v.w *= wt;
        uint2 hi, lo;  split4(v, hi, lo);
        int off = t * (LDX*2) + c * 8;
        *(uint2*)(smem + P1_XHI + off) = hi;
        *(uint2*)(smem + P1_XLO + off) = lo;
    }
    __syncthreads();

    // WMMA: warp w owns m-tile (s) = w, n-tiles (d) 0..3
    const int w = tid >> 5;
    wmma::fragment<wmma::accumulator, 16, 16, 16, float> acc[4];
    #pragma unroll
    for (int nt = 0; nt < 4; ++nt) wmma::fill_fragment(acc[nt], 0.f);
    wmma::fragment<wmma::matrix_a, 16, 16, 16, __nv_bfloat16, wmma::col_major> ahi, alo;
    wmma::fragment<wmma::matrix_b, 16, 16, 16, __nv_bfloat16, wmma::row_major> bhi, blo;

    #pragma unroll
    for (int ks = 0; ks < 4; ++ks) {
        wmma::load_matrix_sync(ahi, Bhi + ks*16*LDC + w*16, LDC);
        wmma::load_matrix_sync(alo, Blo + ks*16*LDC + w*16, LDC);
        #pragma unroll
        for (int nt = 0; nt < 4; ++nt) {
            wmma::load_matrix_sync(bhi, Xhi + ks*16*LDX + nt*16, LDX);
            wmma::load_matrix_sync(blo, Xlo + ks*16*LDX + nt*16, LDX);
            wmma::mma_sync(acc[nt], ahi, bhi, acc[nt]);
            wmma::mma_sync(acc[nt], ahi, blo, acc[nt]);
            wmma::mma_sync(acc[nt], alo, bhi, acc[nt]);
        }
    }
    float* Sdst = g_S + ((size_t)(pair*NCH + ch)) * DH * DS;   // [s][d]
    #pragma unroll
    for (int nt = 0; nt < 4; ++nt)
        wmma::store_matrix_sync(Sdst + w*16*DH + nt*16, acc[nt],
                                DH, wmma::mem_row_major);
}

// =================================================================
// Pass 2: exclusive chunk scan, prefetch depth 2; H pre-split bf16
// =================================================================
__global__ __launch_bounds__(THREADS, 8)
void pass2_kernel() {
    const int pair = blockIdx.x;
    const int idx  = blockIdx.y * THREADS + threadIdx.x;
    const float* Pp = g_P + pair * NCH;
    const size_t base = (size_t)pair * NCH * 2048 + idx;

    float4 Hr   = make_float4(0.f, 0.f, 0.f, 0.f);
    float4 nxt0 = ((const float4*)g_S)[base];
    float4 nxt1 = ((const float4*)g_S)[base + 2048];
    #pragma unroll 4
    for (int ch = 0; ch < NCH; ++ch) {
        float4 cur = nxt0;
        nxt0 = nxt1;
        if (ch + 2 < NCH) nxt1 = ((const float4*)g_S)[base + (size_t)(ch+2)*2048];
        uint2 hi, lo;  split4(Hr, hi, lo);
        ((uint2*)g_Hhi)[base + (size_t)ch*2048] = hi;
        ((uint2*)g_Hlo)[base + (size_t)ch*2048] = lo;
        const float P = Pp[ch];
        Hr.x = P*Hr.x + cur.x;  Hr.y = P*Hr.y + cur.y;
        Hr.z = P*Hr.z + cur.z;  Hr.w = P*Hr.w + cur.w;
    }
}

// =================================================================
// Pass 3 (WMMA):
//   W-warps (0-3): W[t,s'] = C . B^T (causal tile skip)
//   Y-warps (4-7): Y1[t,d] = C . H'
//   epilogue decay/mask; GEMM2 fp32: Y = Y1 + W . x
// H staged via cp.async (pure copy), overlapped with C/B split.
// =================================================================
#define P3_LCP  0
#define P3_GINV 256
#define P3_ELC  512
#define P3_CHI  1024
#define P3_CLO  (P3_CHI + TC*LDC*2)
#define P3_BHI  (P3_CLO + TC*LDC*2)
#define P3_BLO  (P3_BHI + TC*LDC*2)
#define P3_HHI  (P3_BLO + TC*LDC*2)
#define P3_HLO  (P3_HHI + 2*TC*LDH*2)
#define SMEM3   (P3_HLO + 2*TC*LDH*2)    // 107520
#define P3_W    P3_BHI                   // fp32 64 x 68 (aliases Bhi)
#define P3_Y    P3_BLO                   // fp32 64 x 68 (aliases Blo)
#define P3_X    P3_CHI                   // fp32 64 x 64 (aliases Chi)

__global__ __launch_bounds__(THREADS, 2)
void pass3_kernel(const float* __restrict__ x,
                  const float* __restrict__ Bm,
                  const float* __restrict__ Cm,
                  const float* __restrict__ A,
                  const float* __restrict__ dp,
                  float* __restrict__ out) {
    extern __shared__ __align__(128) char smem[];
    float* lcp  = (float*)(smem + P3_LCP);
    float* ginv = (float*)(smem + P3_GINV);
    float* elc  = (float*)(smem + P3_ELC);
    float* Wsh  = (float*)(smem + P3_W);
    float* Ysh  = (float*)(smem + P3_Y);
    float* xs   = (float*)(smem + P3_X);

    const int tid  = threadIdx.x;
    const int ch   = blockIdx.x;
    const int pair = blockIdx.y;
    const int b    = pair / NHD;
    const int hh   = pair % NHD;
    const size_t rowbase = ((size_t)b * LEN + ch * TC) * NHD + hh;

    // ---- H staging first: pure 16B async copies (overlap with split work) ----
    {
        const uint4* Hh16 = (const uint4*)g_Hhi + (size_t)(pair*NCH + ch) * 1024;
        const uint4* Hl16 = (const uint4*)g_Hlo + (size_t)(pair*NCH + ch) * 1024;
        unsigned hb = smem_u32(smem + P3_HHI);
        unsigned lb = smem_u32(smem + P3_HLO);
        #pragma unroll
        for (int j = 0; j < 4; ++j) {
            int i = tid + j * THREADS;          // [0,1024): s = i>>3, c = i&7
            int s = i >> 3, c = i & 7;
            unsigned off = s * (LDH*2) + c * 16;
            cpa16(hb + off, Hh16 + i);
            cpa16(lb + off, Hl16 + i);
        }
        asm volatile("cp.async.commit_group;\n" ::: "memory");
    }

    if (tid < TC) {
        float la = neg_sp_abs(A[rowbase + (size_t)tid * NHD], dp[hh]);
        lcp[tid]  = la;
        ginv[tid] = fminf(__expf(-la), 1e30f);
    }
    __syncthreads();
    scan64(lcp, tid);
    if (tid < TC) elc[tid] = __expf(lcp[tid]);

    // stage C and B [t][k] bf16 hi/lo
    for (int i = tid; i < TC * 32; i += THREADS) {
        int t = i >> 5, c4 = i & 31;
        float4 vc = ((const float4*)(Cm + (rowbase + (size_t)t*NHD) * DS))[c4];
        float4 vb = ((const float4*)(Bm + (rowbase + (size_t)t*NHD) * DS))[c4];
        uint2 hi, lo;
        int off = t * (LDC*2) + c4 * 8;
        split4(vc, hi, lo);
        *(uint2*)(smem + P3_CHI + off) = hi;
        *(uint2*)(smem + P3_CLO + off) = lo;
        split4(vb, hi, lo);
        *(uint2*)(smem + P3_BHI + off) = hi;
        *(uint2*)(smem + P3_BLO + off) = lo;
    }
    // preload x into registers (dumped post-GEMM1 over Chi)
    float4 xr[4];
    #pragma unroll
    for (int j = 0; j < 4; ++j) {
        int i = tid + j * THREADS;
        int t = i >> 4, c = i & 15;
        xr[j] = ((const float4*)(x + (rowbase + (size_t)t*NHD) * DH))[c];
    }
    asm volatile("cp.async.wait_group 0;\n" ::: "memory");
    __syncthreads();

    // ---- GEMM1 ----
    const int w = tid >> 5;
    wmma::fragment<wmma::accumulator, 16, 16, 16, float> acc[4];
    #pragma unroll
    for (int nt = 0; nt < 4; ++nt) wmma::fill_fragment(acc[nt], 0.f);
    {
        wmma::fragment<wmma::matrix_a, 16, 16, 16, __nv_bfloat16, wmma::row_major> ahi, alo;
        const __nv_bfloat16* Cb = (const __nv_bfloat16*)(smem + P3_CHI);
        const __nv_bfloat16* Cl = (const __nv_bfloat16*)(smem + P3_CLO);
        if (w < 4) {   // W = C . B^T  (causal skip)
            const __nv_bfloat16* Db = (const __nv_bfloat16*)(smem + P3_BHI);
            const __nv_bfloat16* Dl = (const __nv_bfloat16*)(smem + P3_BLO);
            wmma::fragment<wmma::matrix_b, 16, 16, 16, __nv_bfloat16, wmma::col_major> bhi, blo;
            #pragma unroll
            for (int ks = 0; ks < 8; ++ks) {
                wmma::load_matrix_sync(ahi, Cb + w*16*LDC + ks*16, LDC);
                wmma::load_matrix_sync(alo, Cl + w*16*LDC + ks*16, LDC);
                #pragma unroll
                for (int nt = 0; nt < 4; ++nt) {
                    if (nt > w) break;
                    wmma::load_matrix_sync(bhi, Db + nt*16*LDC + ks*16, LDC);
                    wmma::load_matrix_sync(blo, Dl + nt*16*LDC + ks*16, LDC);
                    wmma::mma_sync(acc[nt], ahi, bhi, acc[nt]);
                    wmma::mma_sync(acc[nt], ahi, blo, acc[nt]);
                    wmma::mma_sync(acc[nt], alo, bhi, acc[nt]);
                }
            }
        } else {       // Y1 = C . H'
            const int mt = w - 4;
            const __nv_bfloat16* Hb = (const __nv_bfloat16*)(smem + P3_HHI);
            const __nv_bfloat16* Hl = (const __nv_bfloat16*)(smem + P3_HLO);
            wmma::fragment<wmma::matrix_b, 16, 16, 16, __nv_bfloat16, wmma::row_major> bhi, blo;
            #pragma unroll
            for (int ks = 0; ks < 8; ++ks) {
                wmma::load_matrix_sync(ahi, Cb + mt*16*LDC + ks*16, LDC);
                wmma::load_matrix_sync(alo, Cl + mt*16*LDC + ks*16, LDC);
                #pragma unroll
                for (int nt = 0; nt < 4; ++nt) {
                    wmma::load_matrix_sync(bhi, Hb + ks*16*LDH + nt*16, LDH);
                    wmma::load_matrix_sync(blo, Hl + ks*16*LDH + nt*16, LDH);
                    wmma::mma_sync(acc[nt], ahi, bhi, acc[nt]);
                    wmma::mma_sync(acc[nt], ahi, blo, acc[nt]);
                    wmma::mma_sync(acc[nt], alo, bhi, acc[nt]);
                }
            }
        }
    }
    __syncthreads();   // all reads of C/B/H done before aliasing stores

    if (w < 4) {
        #pragma unroll
        for (int nt = 0; nt < 4; ++nt) {
            if (nt > w) break;
            wmma::store_matrix_sync(Wsh + w*16*LDW + nt*16, acc[nt],
                                    LDW, wmma::mem_row_major);
        }
    } else {
        #pragma unroll
        for (int nt = 0; nt < 4; ++nt)
            wmma::store_matrix_sync(Ysh + (w-4)*16*LDW + nt*16, acc[nt],
                                    LDW, wmma::mem_row_major);
    }
    #pragma unroll
    for (int j = 0; j < 4; ++j) ((float4*)xs)[tid + j * THREADS] = xr[j];
    __syncthreads();

    // ---- epilogue: decay/mask W, scale Y1 ----
    {
        const int t  = tid >> 2;
        const int s0 = (tid & 3) * 16;
        float f = (s0 <= t) ? __expf(lcp[t] - lcp[s0]) : 0.f;
        float* wr = Wsh + t * LDW + s0;
        float* yr = Ysh + t * LDW + s0;
        const float et = elc[t];
        #pragma unroll
        for (int i2 = 0; i2 < 16; ++i2) {
            int s = s0 + i2;
            if (i2) f *= ginv[s];
            wr[i2] = (s <= t) ? f * wr[i2] : 0.f;
            yr[i2] = et * yr[i2];
        }
    }
    __syncthreads();

    // ---- GEMM2: Y = Y1 + W . x  (causal, fp32) ----
    const int ty = tid >> 4, tx = tid & 15;
    float ya[4][4];
    #pragma unroll
    for (int i = 0; i < 4; ++i) {
        float4 yv = *(const float4*)(Ysh + (4*ty + i) * LDW + 4*tx);
        ya[i][0] = yv.x; ya[i][1] = yv.y; ya[i][2] = yv.z; ya[i][3] = yv.w;
    }
    for (int s4 = 0; s4 <= ty; ++s4) {
        float4 Wf[4], xf[4];
        #pragma unroll
        for (int i = 0; i < 4; ++i)
            Wf[i] = *(const float4*)(Wsh + (4*ty + i) * LDW + 4*s4);
        #pragma unroll
        for (int k = 0; k < 4; ++k)
            xf[k] = *(const float4*)(xs + (4*s4 + k) * DH + 4*tx);
        #pragma unroll
        for (int i = 0; i < 4; ++i) {
            const float w0 = Wf[i].x, w1 = Wf[i].y, w2 = Wf[i].z, w3 = Wf[i].w;
            ya[i][0] += w0*xf[0].x + w1*xf[1].x + w2*xf[2].x + w3*xf[3].x;
            ya[i][1] += w0*xf[0].y + w1*xf[1].y + w2*xf[2].y + w3*xf[3].y;
            ya[i][2] += w0*xf[0].z + w1*xf[1].z + w2*xf[2].z + w3*xf[3].z;
            ya[i][3] += w0*xf[0].w + w1*xf[1].w + w2*xf[2].w + w3*xf[3].w;
        }
    }
    #pragma unroll
    for (int i = 0; i < 4; ++i) {
        float* yout = out + (rowbase + (size_t)(4*ty + i) * NHD) * DH + 4*tx;
        *(float4*)yout = make_float4(ya[i][0], ya[i][1], ya[i][2], ya[i][3]);
    }
}

// ------------- launch -------------
extern "C" void kernel_launch(void* const* d_in, const int* in_sizes, int n_in,
                              void* d_out, int out_size) {
    const float* x  = (const float*)d_in[0];
    const float* A  = (const float*)d_in[1];
    const float* Bm = (const float*)d_in[2];
    const float* Cm = (const float*)d_in[3];
    const float* dp = (const float*)d_in[4];
    (void)in_sizes; (void)n_in; (void)out_size;

    cudaFuncSetAttribute(pass1_kernel, cudaFuncAttributeMaxDynamicSharedMemorySize, SMEM1);
    cudaFuncSetAttribute(pass3_kernel, cudaFuncAttributeMaxDynamicSharedMemorySize, SMEM3);

    dim3 grid(NCH, NPAIR);
    pass1_kernel<<<grid, THREADS, SMEM1>>>(x, Bm, A, dp);
    pass2_kernel<<<dim3(NPAIR, 8), THREADS>>>();
    pass3_kernel<<<grid, THREADS, SMEM3>>>(x, Bm, Cm, A, dp, (float*)d_out);
}